// round 3
// baseline (speedup 1.0000x reference)
#include <cuda_runtime.h>
#include <math.h>

// ---------------------------------------------------------------------------
// Tree-reduce with fused conv gate, fp32, packed f32x2 FMA.
//
// Layout v3: warp-uniform channels (w reads are LDS broadcasts),
// lanes own positions, accumulators are position-pairs packed in f32x2.
//   - x tile [k][pos] in smem, natural contiguous -> LDS.128 = 2 packed pairs
//   - w tile stored PRE-DUPLICATED (w,w) -> LDS.64 broadcast per channel row
// Block tile: 256 positions x 16 base channels (x3 gates). 256 threads.
// Warp wid: channels cblk*16 + wid*2 + {0,1}; lane: positions {4l..4l+3} and
// {128+4l..128+4l+3}. Micro: 4 pos-pairs x 6 rows = 24 f32x2 accumulators.
// ---------------------------------------------------------------------------

#define BATCH 16
#define CCH   512
#define LMAX  4096
#define KDIM  1024
#define SLAB  8192
#define BM    256     // output positions per block
#define BK    16      // K-tile
#define XROW  260     // x smem row stride (words), mult of 4 for LDS.128
#define WROW  100     // w smem row stride (words), duplicated pairs, mult of 2

__device__ float g_buf[(size_t)BATCH * SLAB * CCH];   // 268 MB scratch
__device__ float g_wp[1536 * KDIM];                   // permuted W

typedef unsigned long long u64;

__device__ __forceinline__ void ffma2(u64& d, u64 a, u64 b) {
    asm("fma.rn.f32x2 %0, %1, %2, %0;" : "+l"(d) : "l"(a), "l"(b));
}
__device__ __forceinline__ float2 unpk(u64 v) {
    union { u64 u; float2 f; } c; c.u = v; return c.f;
}

// ---------------------------------------------------------------------------
__global__ void permute_w(const float* __restrict__ W) {
    int i = blockIdx.x * blockDim.x + threadIdx.x;
    if (i >= 1536 * KDIM) return;
    int o  = i >> 10;
    int kp = i & 1023;          // kp = kk*512 + c
    int kk = kp >> 9;
    int c  = kp & 511;
    g_wp[i] = W[o * KDIM + c * 2 + kk];
}

// ---------------------------------------------------------------------------
// Transpose h[b][c][j] into position-major layout, splitting destinations:
//   j <  M        -> staging (off_1 region)   [feeds the level-0 partial conv]
//   M <= j < N    -> cur region, position j - M/2   [the raw suffix]
// ---------------------------------------------------------------------------
__global__ void transpose_init(const float* __restrict__ h,
                               const int* __restrict__ Np) {
    __shared__ float tile[32][33];
    int b = blockIdx.z;
    int N = Np[b];
    int s = 31 - __clz(N);
    int Nfp2 = 1 << s;
    int M2 = N - Nfp2;          // M/2
    int M  = 2 * M2;
    int j0 = blockIdx.x * 32;
    int c0 = blockIdx.y * 32;
    if (j0 >= N) return;

    int tx = threadIdx.x & 31, ty = threadIdx.x >> 5;
    const float* hb = h + (size_t)b * CCH * LMAX;
    #pragma unroll
    for (int i = 0; i < 4; i++) {
        int c = c0 + ty + i * 8;
        tile[ty + i * 8][tx] = hb[(size_t)c * LMAX + j0 + tx];
    }
    __syncthreads();
    float* bufb = g_buf + (size_t)b * SLAB * CCH;
    #pragma unroll
    for (int i = 0; i < 4; i++) {
        int j = j0 + ty + i * 8;
        float v = tile[tx][ty + i * 8];
        int c = c0 + tx;
        if (j < M) {
            bufb[(size_t)(4096 + j) * CCH + c] = v;        // staging @ off_1
        } else if (j < N) {
            bufb[(size_t)(j - M2) * CCH + c] = v;          // cur @ off_0
        }
    }
}

// ---------------------------------------------------------------------------
// One conv-reduce level. level==0: partial fold (P = N - Nfp2, input=staging);
// level>=1: tree level (P = (Nfp2 >> (level-1)) / 2).
// ---------------------------------------------------------------------------
__global__ __launch_bounds__(256)
void conv_level(const int* __restrict__ Np, const float* __restrict__ bias,
                int level, int off_in, int off_out, int maxP) {
    int b = blockIdx.z;
    int N = Np[b];
    int s = 31 - __clz(N);
    int Nfp2 = 1 << s;
    int P;
    if (level == 0) {
        P = N - Nfp2;
    } else {
        int len_in = Nfp2 >> (level - 1);
        P = (len_in >= 2) ? (len_in >> 1) : 0;
    }
    int p0 = blockIdx.x * BM;
    if (p0 >= P) return;

    const float* __restrict__ in  = g_buf + ((size_t)b * SLAB + off_in)  * CCH;
    float*       __restrict__ out = g_buf + ((size_t)b * SLAB + off_out) * CCH;
    int cblk = blockIdx.y;   // 0..31, 16 base channels each

    __shared__ float xs[BK][XROW];    // x tile [k][pos 0..255]
    __shared__ float ws[BK][WROW];    // w tile, duplicated: [k][2*row + {0,1}]

    int tid  = threadIdx.x;
    int lane = tid & 31;
    int wid  = tid >> 5;     // warp 0..7 -> base channels wid*2, wid*2+1

    u64 acc2[4][6];          // [pos-pair][gate*2+ch], packed (posEven, posOdd)
    #pragma unroll
    for (int p = 0; p < 4; p++)
        #pragma unroll
        for (int q = 0; q < 6; q++) acc2[p][q] = 0ull;

    // --- global load plans (register-staged prefetch) ---
    // x: 256 pos x 16 k per tile = 1024 float4, 4 per thread.
    // mapping: idx = tid + a*256 -> pos = idx>>2, kq = idx&3 (coalesced 64B/pos)
    const float4* xg[4]; int xpos[4], xkq[4];
    #pragma unroll
    for (int a = 0; a < 4; a++) {
        int idx = tid + a * 256;
        int pos = idx >> 2, kq = idx & 3;
        int lc = min(p0 + pos, maxP - 1);
        xg[a]  = (const float4*)(in + (size_t)(2 * lc) * CCH) + kq;
        xpos[a] = pos; xkq[a] = kq;
    }
    // w: 48 rows x 16 k per tile = 192 float4, threads 0..191 take one each
    const float4* wg = 0; int wrow = 0, wkq = 0;
    if (tid < 192) {
        wrow = tid >> 2; wkq = tid & 3;
        int grow = (wrow >> 4) * 512 + cblk * 16 + (wrow & 15);
        wg = (const float4*)(g_wp + (size_t)grow * KDIM) + wkq;
    }

    float4 xr[4], wr;
    #pragma unroll
    for (int a = 0; a < 4; a++) xr[a] = xg[a][0];
    if (tid < 192) wr = wg[0];

    const int NT = KDIM / BK;   // 64
    for (int t = 0; t < NT; t++) {
        #pragma unroll
        for (int a = 0; a < 4; a++) {
            int k4 = xkq[a] * 4;
            xs[k4 + 0][xpos[a]] = xr[a].x;
            xs[k4 + 1][xpos[a]] = xr[a].y;
            xs[k4 + 2][xpos[a]] = xr[a].z;
            xs[k4 + 3][xpos[a]] = xr[a].w;
        }
        if (tid < 192) {
            int k4 = wkq * 4;
            *(float2*)&ws[k4 + 0][2 * wrow] = make_float2(wr.x, wr.x);
            *(float2*)&ws[k4 + 1][2 * wrow] = make_float2(wr.y, wr.y);
            *(float2*)&ws[k4 + 2][2 * wrow] = make_float2(wr.z, wr.z);
            *(float2*)&ws[k4 + 3][2 * wrow] = make_float2(wr.w, wr.w);
        }
        __syncthreads();
        if (t + 1 < NT) {
            #pragma unroll
            for (int a = 0; a < 4; a++) xr[a] = xg[a][(t + 1) * 4];
            if (tid < 192) wr = wg[(t + 1) * 4];
        }
        #pragma unroll
        for (int k = 0; k < BK; k++) {
            // 4 packed position-pairs: lanes cover contiguous 512B per LDS.128
            ulonglong2 xa = *(const ulonglong2*)&xs[k][4 * lane];
            ulonglong2 xb = *(const ulonglong2*)&xs[k][128 + 4 * lane];
            // 6 broadcast duplicated w operands (all lanes same address)
            u64 w0 = *(const u64*)&ws[k][2 * (0  + wid * 2)];
            u64 w1 = *(const u64*)&ws[k][2 * (1  + wid * 2)];
            u64 w2 = *(const u64*)&ws[k][2 * (16 + wid * 2)];
            u64 w3 = *(const u64*)&ws[k][2 * (17 + wid * 2)];
            u64 w4 = *(const u64*)&ws[k][2 * (32 + wid * 2)];
            u64 w5 = *(const u64*)&ws[k][2 * (33 + wid * 2)];
            u64 xv[4] = {xa.x, xa.y, xb.x, xb.y};
            #pragma unroll
            for (int p = 0; p < 4; p++) {
                ffma2(acc2[p][0], xv[p], w0);
                ffma2(acc2[p][1], xv[p], w1);
                ffma2(acc2[p][2], xv[p], w2);
                ffma2(acc2[p][3], xv[p], w3);
                ffma2(acc2[p][4], xv[p], w4);
                ffma2(acc2[p][5], xv[p], w5);
            }
        }
        __syncthreads();
    }

    // --- fused gate epilogue ---
    // pair p covers positions: p<2 -> 4*lane + 2p (+1); p>=2 -> 128 + 4*lane + 2(p-2)
    int chb = cblk * 16 + wid * 2;
    float bl0 = bias[chb],          bl1 = bias[chb + 1];
    float br0 = bias[512 + chb],    br1 = bias[512 + chb + 1];
    float bg0 = bias[1024 + chb],   bg1 = bias[1024 + chb + 1];
    #pragma unroll
    for (int p = 0; p < 4; p++) {
        int pbase = (p < 2) ? (4 * lane + 2 * p) : (128 + 4 * lane + 2 * (p - 2));
        float2 c0 = unpk(acc2[p][0]);   // l gate, ch0: (posE, posO)
        float2 c1 = unpk(acc2[p][1]);   // l gate, ch1
        float2 c2 = unpk(acc2[p][2]);   // r gate, ch0
        float2 c3 = unpk(acc2[p][3]);   // r gate, ch1
        float2 c4 = unpk(acc2[p][4]);   // g gate, ch0
        float2 c5 = unpk(acc2[p][5]);   // g gate, ch1
        float lc0[2] = {c0.x, c0.y}, lc1[2] = {c1.x, c1.y};
        float rc0[2] = {c2.x, c2.y}, rc1[2] = {c3.x, c3.y};
        float gc0[2] = {c4.x, c4.y}, gc1[2] = {c5.x, c5.y};
        #pragma unroll
        for (int e = 0; e < 2; e++) {
            int l = p0 + pbase + e;
            if (l >= P) continue;
            float lv0 = lc0[e] + bl0;
            float lv1 = lc1[e] + bl1;
            float rv0 = tanhf(rc0[e] + br0);
            float rv1 = tanhf(rc1[e] + br1);
            float gv0 = 1.0f / (1.0f + expf(-(gc0[e] + bg0)));
            float gv1 = 1.0f / (1.0f + expf(-(gc1[e] + bg1)));
            float2 ov;
            ov.x = lv0 * gv0 + rv0 * (1.0f - gv0);
            ov.y = lv1 * gv1 + rv1 * (1.0f - gv1);
            *(float2*)&out[(size_t)l * CCH + chb] = ov;
        }
    }
}

// ---------------------------------------------------------------------------
__global__ void extract(float* __restrict__ out, const int* __restrict__ Np) {
    int b = blockIdx.x;
    int N = Np[b];
    int s = 31 - __clz(N);
    int off = SLAB - (SLAB >> s);
    int c = threadIdx.x;
    out[b * CCH + c] = g_buf[((size_t)b * SLAB + off) * CCH + c];
}

// ---------------------------------------------------------------------------
extern "C" void kernel_launch(void* const* d_in, const int* in_sizes, int n_in,
                              void* d_out, int out_size) {
    const float* h    = (const float*)d_in[0];
    const float* W    = (const float*)d_in[1];
    const float* bias = (const float*)d_in[2];
    const int*   N    = (const int*)d_in[3];
    float* out = (float*)d_out;

    permute_w<<<(1536 * KDIM + 255) / 256, 256>>>(W);

    dim3 tg(LMAX / 32, CCH / 32, BATCH);
    transpose_init<<<tg, 256>>>(h, N);

    // level 0: partial fold of the first M elements (P_b = N - Nfp2 <= 2047)
    {
        int maxP = 2048;
        dim3 g((maxP + BM - 1) / BM, 32, BATCH);
        conv_level<<<g, 256>>>(N, bias, 0, 4096, 0, maxP);
    }

    // tree levels
    int off_in = 0;
    for (int k = 1; k <= 12; k++) {
        int off_out = SLAB - (SLAB >> k);
        int maxP = LMAX >> k;
        dim3 g((maxP + BM - 1) / BM, 32, BATCH);
        conv_level<<<g, 256>>>(N, bias, k, off_in, off_out, maxP);
        off_in = off_out;
    }

    extract<<<BATCH, CCH>>>(out, N);
}

// round 5
// speedup vs baseline: 2.1115x; 2.1115x over previous
#include <cuda_runtime.h>
#include <cuda_bf16.h>
#include <math.h>

// ---------------------------------------------------------------------------
// Tree-reduce with fused conv gate — TENSOR CORE version (bf16x3 split).
//   Per level: lrg[o,l] = sum_{c,k} in[c,2l+k] * W[o,c,k] + b[o]
//   out = l*sig(g) + tanh(r)*(1-sig(g)).
// Activations & W stored as bf16 (hi, lo) plane pairs; each GEMM computed as
// xh*wh + xh*wl + xl*wh with fp32 accumulators (mma.sync.m16n8k16.bf16).
//
// Block: 256 positions x 96 rows (32 base ch x 3 gates), 256 threads.
// Warp grid 4(M) x 2(N): warp = 64 pos x 48 rows = 4 m16-tiles x 6 n8-tiles.
// cp.async double-buffered smem tiles (BK=32), ldmatrix fragment loads.
//
// R4 bugfix: w-load plan used (idx & 383) for idx mod 384 — 384 is not a
// power of two, bit 7 was cleared, leaving w smem rows 32..63 uninitialized
// (NaN via B fragments). Now computed with an explicit subtract.
// ---------------------------------------------------------------------------

#define BATCH 16
#define CCH   512
#define LMAX  4096
#define KDIM  1024
#define SLAB  8192
#define BM    256
#define BK    32
#define WRWS  96
#define PITCH 40                 // smem row pitch in bf16 (80 bytes)
#define NT    (KDIM / BK)        // 32 k-tiles

#define XB (BM * PITCH * 2)      // 20480 B per x plane per buffer
#define WB (WRWS * PITCH * 2)    // 7680  B per w plane per buffer
#define SMEM_TOTAL (4 * XB + 4 * WB)   // 112640 B

__device__ __nv_bfloat16 g_xh[(size_t)BATCH * SLAB * CCH];
__device__ __nv_bfloat16 g_xl[(size_t)BATCH * SLAB * CCH];
__device__ __nv_bfloat16 g_wh[1536 * KDIM];
__device__ __nv_bfloat16 g_wl[1536 * KDIM];

typedef unsigned u32;

__device__ __forceinline__ void cpa16(u32 dst, const void* src) {
    asm volatile("cp.async.cg.shared.global [%0], [%1], 16;" :: "r"(dst), "l"(src));
}
__device__ __forceinline__ void cp_commit() {
    asm volatile("cp.async.commit_group;");
}
template<int NW> __device__ __forceinline__ void cp_wait() {
    asm volatile("cp.async.wait_group %0;" :: "n"(NW));
}
__device__ __forceinline__ void ldsm4(u32& r0, u32& r1, u32& r2, u32& r3, u32 a) {
    asm volatile("ldmatrix.sync.aligned.m8n8.x4.shared.b16 {%0,%1,%2,%3}, [%4];"
                 : "=r"(r0), "=r"(r1), "=r"(r2), "=r"(r3) : "r"(a));
}
__device__ __forceinline__ void ldsm2(u32& r0, u32& r1, u32 a) {
    asm volatile("ldmatrix.sync.aligned.m8n8.x2.shared.b16 {%0,%1}, [%2];"
                 : "=r"(r0), "=r"(r1) : "r"(a));
}
__device__ __forceinline__ void mma16816(float* d, const u32* a, const u32* b) {
    asm volatile("mma.sync.aligned.m16n8k16.row.col.f32.bf16.bf16.f32 "
                 "{%0,%1,%2,%3},{%4,%5,%6,%7},{%8,%9},{%0,%1,%2,%3};"
                 : "+f"(d[0]), "+f"(d[1]), "+f"(d[2]), "+f"(d[3])
                 : "r"(a[0]), "r"(a[1]), "r"(a[2]), "r"(a[3]),
                   "r"(b[0]), "r"(b[1]));
}
__device__ __forceinline__ void split_bf16(float v, __nv_bfloat16& h, __nv_bfloat16& l) {
    h = __float2bfloat16(v);
    l = __float2bfloat16(v - __bfloat162float(h));
}

// ---------------------------------------------------------------------------
__global__ void permute_w(const float* __restrict__ W) {
    int i = blockIdx.x * blockDim.x + threadIdx.x;
    if (i >= 1536 * KDIM) return;
    int o  = i >> 10;
    int kp = i & 1023;          // kp = kk*512 + c
    int kk = kp >> 9;
    int c  = kp & 511;
    float w = W[o * KDIM + c * 2 + kk];
    split_bf16(w, g_wh[i], g_wl[i]);
}

// ---------------------------------------------------------------------------
// Transpose h[b][c][j] into position-major bf16 hi/lo planes:
//   j <  M      -> staging (row 4096+j)   [feeds the level-0 partial conv]
//   M <= j < N  -> cur region, row j - M/2   [the raw suffix]
// ---------------------------------------------------------------------------
__global__ void transpose_init(const float* __restrict__ h,
                               const int* __restrict__ Np) {
    __shared__ float tile[32][33];
    int b = blockIdx.z;
    int N = Np[b];
    int s = 31 - __clz(N);
    int Nfp2 = 1 << s;
    int M2 = N - Nfp2;
    int M  = 2 * M2;
    int j0 = blockIdx.x * 32;
    int c0 = blockIdx.y * 32;
    if (j0 >= N) return;

    int tx = threadIdx.x & 31, ty = threadIdx.x >> 5;
    const float* hb = h + (size_t)b * CCH * LMAX;
    #pragma unroll
    for (int i = 0; i < 4; i++) {
        int c = c0 + ty + i * 8;
        tile[ty + i * 8][tx] = hb[(size_t)c * LMAX + j0 + tx];
    }
    __syncthreads();
    size_t slab = (size_t)b * SLAB;
    #pragma unroll
    for (int i = 0; i < 4; i++) {
        int j = j0 + ty + i * 8;
        float v = tile[tx][ty + i * 8];
        int c = c0 + tx;
        size_t idx;
        if (j < M)        idx = (slab + 4096 + j) * CCH + c;
        else if (j < N)   idx = (slab + (j - M2)) * CCH + c;
        else continue;
        __nv_bfloat16 hv, lv;
        split_bf16(v, hv, lv);
        g_xh[idx] = hv;
        g_xl[idx] = lv;
    }
}

// ---------------------------------------------------------------------------
__global__ __launch_bounds__(256)
void conv_mma(const int* __restrict__ Np, const float* __restrict__ bias,
              int level, int off_in, int off_out, int maxP) {
    extern __shared__ char smem[];
    int b = blockIdx.z;
    int N = Np[b];
    int s = 31 - __clz(N);
    int Nfp2 = 1 << s;
    int P;
    if (level == 0) P = N - Nfp2;
    else { int li = Nfp2 >> (level - 1); P = (li >= 2) ? (li >> 1) : 0; }
    int p0 = blockIdx.x * BM;
    if (p0 >= P) return;

    const __nv_bfloat16* inh = g_xh + ((size_t)b * SLAB + off_in) * CCH;
    const __nv_bfloat16* inl = g_xl + ((size_t)b * SLAB + off_in) * CCH;
    __nv_bfloat16* outh = g_xh + ((size_t)b * SLAB + off_out) * CCH;
    __nv_bfloat16* outl = g_xl + ((size_t)b * SLAB + off_out) * CCH;
    int cblk = blockIdx.y;   // 0..15

    u32 sb = (u32)__cvta_generic_to_shared(smem);
    int tid = threadIdx.x, lane = tid & 31, wid = tid >> 5;
    int wm = wid >> 1, wn = wid & 1;

    // ---- global->smem async load plans ----
    const char* xsrc[8]; u32 xdst0[8];
    #pragma unroll
    for (int a = 0; a < 8; a++) {
        int idx = tid + a * 256;               // 2048 chunks
        int pl = idx >> 10, pos = (idx & 1023) >> 2, ch = idx & 3;
        int lc = min(p0 + pos, maxP - 1);
        const __nv_bfloat16* base = pl ? inl : inh;
        xsrc[a]  = (const char*)base + (size_t)(2 * lc) * 1024 + ch * 16;
        xdst0[a] = (pl ? 2 * XB : 0) + pos * 80 + ch * 16;
    }
    const char* wsrc[3]; u32 wdst0[3];
    #pragma unroll
    for (int a = 0; a < 3; a++) {
        int idx = tid + a * 256;               // 768 chunks
        int pl  = (idx >= 384);
        int rem = idx - (pl ? 384 : 0);        // idx mod 384 (384 != pow2!)
        int r   = rem >> 2, ch = rem & 3;
        int grow = (r >> 5) * 512 + cblk * 32 + (r & 31);
        wsrc[a]  = (const char*)(pl ? g_wl : g_wh) + (size_t)grow * 2048 + ch * 16;
        wdst0[a] = 4 * XB + (pl ? 2 * WB : 0) + r * 80 + ch * 16;
    }

    // ---- fragment base addresses ----
    int lane15 = lane & 15;
    u32 a_h = sb + (u32)((wm * 64 + lane15) * 80 + (lane >> 4) * 16);
    u32 a_l = a_h + 2 * XB;
    u32 b_h = sb + 4 * XB + (u32)((wn * 16 + (lane & 7)) * 80 + ((lane >> 3) & 1) * 16);
    u32 b_l = b_h + 2 * WB;

    float acc[4][3][2][4];
    #pragma unroll
    for (int mt = 0; mt < 4; mt++)
        #pragma unroll
        for (int g = 0; g < 3; g++)
            #pragma unroll
            for (int hf = 0; hf < 2; hf++)
                #pragma unroll
                for (int q = 0; q < 4; q++) acc[mt][g][hf][q] = 0.0f;

    // prologue: tile 0 into buffer 0
    #pragma unroll
    for (int a = 0; a < 8; a++) cpa16(sb + xdst0[a], xsrc[a]);
    #pragma unroll
    for (int a = 0; a < 3; a++) cpa16(sb + wdst0[a], wsrc[a]);
    cp_commit();

    for (int t = 0; t < NT; t++) {
        int buf = t & 1;
        if (t + 1 < NT) {
            int nb = (t + 1) & 1;
            size_t off = (size_t)(t + 1) * 64;
            #pragma unroll
            for (int a = 0; a < 8; a++) cpa16(sb + xdst0[a] + nb * XB, xsrc[a] + off);
            #pragma unroll
            for (int a = 0; a < 3; a++) cpa16(sb + wdst0[a] + nb * WB, wsrc[a] + off);
            cp_commit();
            cp_wait<1>();
        } else {
            cp_wait<0>();
        }
        __syncthreads();

        u32 xoff = buf * XB, woff = buf * WB;
        #pragma unroll
        for (int j = 0; j < 2; j++) {
            u32 bh[3][2][2], bl[3][2][2];
            #pragma unroll
            for (int g = 0; g < 3; g++)
                #pragma unroll
                for (int hf = 0; hf < 2; hf++) {
                    u32 ba = (u32)(g * 2560 + hf * 640 + j * 32);
                    ldsm2(bh[g][hf][0], bh[g][hf][1], b_h + woff + ba);
                    ldsm2(bl[g][hf][0], bl[g][hf][1], b_l + woff + ba);
                }
            #pragma unroll
            for (int mt = 0; mt < 4; mt++) {
                u32 ah[4], al[4];
                u32 aa = (u32)(mt * 1280 + j * 32);
                ldsm4(ah[0], ah[1], ah[2], ah[3], a_h + xoff + aa);
                ldsm4(al[0], al[1], al[2], al[3], a_l + xoff + aa);
                #pragma unroll
                for (int g = 0; g < 3; g++)
                    #pragma unroll
                    for (int hf = 0; hf < 2; hf++) {
                        float* d = acc[mt][g][hf];
                        mma16816(d, ah, bh[g][hf]);
                        mma16816(d, ah, bl[g][hf]);
                        mma16816(d, al, bh[g][hf]);
                    }
            }
        }
        __syncthreads();
    }

    // ---- fused gate epilogue; write next level's bf16 hi/lo planes ----
    int gid = lane >> 2, tig = lane & 3;
    #pragma unroll
    for (int mt = 0; mt < 4; mt++) {
        #pragma unroll
        for (int hf = 0; hf < 2; hf++) {
            int ch = cblk * 32 + wn * 16 + hf * 8 + 2 * tig;
            float bl0 = bias[ch],        bl1 = bias[ch + 1];
            float br0 = bias[512 + ch],  br1 = bias[513 + ch];
            float bg0 = bias[1024 + ch], bg1 = bias[1025 + ch];
            #pragma unroll
            for (int rs = 0; rs < 2; rs++) {
                int pos = p0 + wm * 64 + mt * 16 + rs * 8 + gid;
                if (pos >= P) continue;
                float lv0 = acc[mt][0][hf][rs * 2 + 0] + bl0;
                float lv1 = acc[mt][0][hf][rs * 2 + 1] + bl1;
                float rv0 = tanhf(acc[mt][1][hf][rs * 2 + 0] + br0);
                float rv1 = tanhf(acc[mt][1][hf][rs * 2 + 1] + br1);
                float gv0 = 1.0f / (1.0f + expf(-(acc[mt][2][hf][rs * 2 + 0] + bg0)));
                float gv1 = 1.0f / (1.0f + expf(-(acc[mt][2][hf][rs * 2 + 1] + bg1)));
                float v0 = lv0 * gv0 + rv0 * (1.0f - gv0);
                float v1 = lv1 * gv1 + rv1 * (1.0f - gv1);
                __nv_bfloat162 ph, pl2;
                split_bf16(v0, ph.x, pl2.x);
                split_bf16(v1, ph.y, pl2.y);
                *reinterpret_cast<__nv_bfloat162*>(outh + (size_t)pos * CCH + ch) = ph;
                *reinterpret_cast<__nv_bfloat162*>(outl + (size_t)pos * CCH + ch) = pl2;
            }
        }
    }
}

// ---------------------------------------------------------------------------
__global__ void extract(float* __restrict__ out, const int* __restrict__ Np) {
    int b = blockIdx.x;
    int N = Np[b];
    int s = 31 - __clz(N);
    int off = SLAB - (SLAB >> s);
    int c = threadIdx.x;
    size_t idx = ((size_t)b * SLAB + off) * CCH + c;
    out[b * CCH + c] = __bfloat162float(g_xh[idx]) + __bfloat162float(g_xl[idx]);
}

// ---------------------------------------------------------------------------
extern "C" void kernel_launch(void* const* d_in, const int* in_sizes, int n_in,
                              void* d_out, int out_size) {
    const float* h    = (const float*)d_in[0];
    const float* W    = (const float*)d_in[1];
    const float* bias = (const float*)d_in[2];
    const int*   N    = (const int*)d_in[3];
    float* out = (float*)d_out;

    cudaFuncSetAttribute(conv_mma, cudaFuncAttributeMaxDynamicSharedMemorySize,
                         SMEM_TOTAL);

    permute_w<<<(1536 * KDIM + 255) / 256, 256>>>(W);

    dim3 tg(LMAX / 32, CCH / 32, BATCH);
    transpose_init<<<tg, 256>>>(h, N);

    // level 0: partial fold of the first M elements (P_b = N - Nfp2 <= 2047)
    {
        int maxP = 2048;
        dim3 g((maxP + BM - 1) / BM, 16, BATCH);
        conv_mma<<<g, 256, SMEM_TOTAL>>>(N, bias, 0, 4096, 0, maxP);
    }

    // tree levels
    int off_in = 0;
    for (int k = 1; k <= 12; k++) {
        int off_out = SLAB - (SLAB >> k);
        int maxP = LMAX >> k;
        dim3 g((maxP + BM - 1) / BM, 16, BATCH);
        conv_mma<<<g, 256, SMEM_TOTAL>>>(N, bias, k, off_in, off_out, maxP);
        off_in = off_out;
    }

    extract<<<BATCH, CCH>>>(out, N);
}

// round 6
// speedup vs baseline: 3.6208x; 1.7147x over previous
#include <cuda_runtime.h>
#include <cuda_bf16.h>
#include <math.h>

// ---------------------------------------------------------------------------
// Tree-reduce with fused conv gate — tensor cores (bf16x3 split), v2.
//   xh*wh + xh*wl + xl*wh with fp32 accum (mma.sync.m16n8k16.bf16).
// v2 changes vs round-5 winner:
//   * BM templated via MT (m16-tiles per warp): BM = MT*64.
//     MT=2 (BM=128) main kernel -> 70KB smem, <=128 regs, 2 CTAs/SM.
//     MT=1 (BM=64) for deep levels (maxP <= 64).
//   * MMA term-outer ordering: same-accumulator MMAs spaced by 6 independents.
// ---------------------------------------------------------------------------

#define BATCH 16
#define CCH   512
#define LMAX  4096
#define KDIM  1024
#define SLAB  8192
#define BK    32
#define WRWS  96
#define PITCH 40                  // smem row pitch in bf16 (80 bytes)
#define NT    (KDIM / BK)         // 32 k-tiles
#define WB    (WRWS * PITCH * 2)  // 7680 B per w plane per buffer

__device__ __nv_bfloat16 g_xh[(size_t)BATCH * SLAB * CCH];
__device__ __nv_bfloat16 g_xl[(size_t)BATCH * SLAB * CCH];
__device__ __nv_bfloat16 g_wh[1536 * KDIM];
__device__ __nv_bfloat16 g_wl[1536 * KDIM];

typedef unsigned u32;

__device__ __forceinline__ void cpa16(u32 dst, const void* src) {
    asm volatile("cp.async.cg.shared.global [%0], [%1], 16;" :: "r"(dst), "l"(src));
}
__device__ __forceinline__ void cp_commit() {
    asm volatile("cp.async.commit_group;");
}
template<int NW> __device__ __forceinline__ void cp_wait() {
    asm volatile("cp.async.wait_group %0;" :: "n"(NW));
}
__device__ __forceinline__ void ldsm4(u32& r0, u32& r1, u32& r2, u32& r3, u32 a) {
    asm volatile("ldmatrix.sync.aligned.m8n8.x4.shared.b16 {%0,%1,%2,%3}, [%4];"
                 : "=r"(r0), "=r"(r1), "=r"(r2), "=r"(r3) : "r"(a));
}
__device__ __forceinline__ void ldsm2(u32& r0, u32& r1, u32 a) {
    asm volatile("ldmatrix.sync.aligned.m8n8.x2.shared.b16 {%0,%1}, [%2];"
                 : "=r"(r0), "=r"(r1) : "r"(a));
}
__device__ __forceinline__ void mma16816(float* d, const u32* a, const u32* b) {
    asm volatile("mma.sync.aligned.m16n8k16.row.col.f32.bf16.bf16.f32 "
                 "{%0,%1,%2,%3},{%4,%5,%6,%7},{%8,%9},{%0,%1,%2,%3};"
                 : "+f"(d[0]), "+f"(d[1]), "+f"(d[2]), "+f"(d[3])
                 : "r"(a[0]), "r"(a[1]), "r"(a[2]), "r"(a[3]),
                   "r"(b[0]), "r"(b[1]));
}
__device__ __forceinline__ void split_bf16(float v, __nv_bfloat16& h, __nv_bfloat16& l) {
    h = __float2bfloat16(v);
    l = __float2bfloat16(v - __bfloat162float(h));
}

// ---------------------------------------------------------------------------
__global__ void permute_w(const float* __restrict__ W) {
    int i = blockIdx.x * blockDim.x + threadIdx.x;
    if (i >= 1536 * KDIM) return;
    int o  = i >> 10;
    int kp = i & 1023;
    int kk = kp >> 9;
    int c  = kp & 511;
    float w = W[o * KDIM + c * 2 + kk];
    split_bf16(w, g_wh[i], g_wl[i]);
}

// ---------------------------------------------------------------------------
__global__ void transpose_init(const float* __restrict__ h,
                               const int* __restrict__ Np) {
    __shared__ float tile[32][33];
    int b = blockIdx.z;
    int N = Np[b];
    int s = 31 - __clz(N);
    int Nfp2 = 1 << s;
    int M2 = N - Nfp2;
    int M  = 2 * M2;
    int j0 = blockIdx.x * 32;
    int c0 = blockIdx.y * 32;
    if (j0 >= N) return;

    int tx = threadIdx.x & 31, ty = threadIdx.x >> 5;
    const float* hb = h + (size_t)b * CCH * LMAX;
    #pragma unroll
    for (int i = 0; i < 4; i++) {
        int c = c0 + ty + i * 8;
        tile[ty + i * 8][tx] = hb[(size_t)c * LMAX + j0 + tx];
    }
    __syncthreads();
    size_t slab = (size_t)b * SLAB;
    #pragma unroll
    for (int i = 0; i < 4; i++) {
        int j = j0 + ty + i * 8;
        float v = tile[tx][ty + i * 8];
        int c = c0 + tx;
        size_t idx;
        if (j < M)        idx = (slab + 4096 + j) * CCH + c;
        else if (j < N)   idx = (slab + (j - M2)) * CCH + c;
        else continue;
        __nv_bfloat16 hv, lv;
        split_bf16(v, hv, lv);
        g_xh[idx] = hv;
        g_xl[idx] = lv;
    }
}

// ---------------------------------------------------------------------------
// MT = m16-tiles per warp; block tile = MT*64 positions x 96 rows.
// Warp grid 4(M) x 2(N). 2 CTAs/SM target.
// ---------------------------------------------------------------------------
template<int MT>
__global__ __launch_bounds__(256, 2)
void conv_mma(const int* __restrict__ Np, const float* __restrict__ bias,
              int level, int off_in, int off_out, int maxP) {
    constexpr int BM = MT * 64;
    constexpr int XB = BM * PITCH * 2;          // bytes per x plane per buffer
    constexpr int XCH = MT * 256;               // x chunks per plane per tile
    constexpr int XLD = 2 * MT;                 // x cp.async per thread

    extern __shared__ char smem[];
    int b = blockIdx.z;
    int N = Np[b];
    int s = 31 - __clz(N);
    int Nfp2 = 1 << s;
    int P;
    if (level == 0) P = N - Nfp2;
    else { int li = Nfp2 >> (level - 1); P = (li >= 2) ? (li >> 1) : 0; }
    int p0 = blockIdx.x * BM;
    if (p0 >= P) return;

    const __nv_bfloat16* inh = g_xh + ((size_t)b * SLAB + off_in) * CCH;
    const __nv_bfloat16* inl = g_xl + ((size_t)b * SLAB + off_in) * CCH;
    __nv_bfloat16* outh = g_xh + ((size_t)b * SLAB + off_out) * CCH;
    __nv_bfloat16* outl = g_xl + ((size_t)b * SLAB + off_out) * CCH;
    int cblk = blockIdx.y;

    u32 sb = (u32)__cvta_generic_to_shared(smem);
    int tid = threadIdx.x, lane = tid & 31, wid = tid >> 5;
    int wm = wid >> 1, wn = wid & 1;

    // ---- global->smem async load plans ----
    const char* xsrc[XLD]; u32 xdst0[XLD];
    #pragma unroll
    for (int a = 0; a < XLD; a++) {
        int idx = tid + a * 256;
        int pl  = (idx >= XCH);
        int rem = idx - (pl ? XCH : 0);
        int pos = rem >> 2, ch = rem & 3;
        int lc = min(p0 + pos, maxP - 1);
        const __nv_bfloat16* base = pl ? inl : inh;
        xsrc[a]  = (const char*)base + (size_t)(2 * lc) * 1024 + ch * 16;
        xdst0[a] = (pl ? 2 * XB : 0) + pos * 80 + ch * 16;
    }
    const char* wsrc[3]; u32 wdst0[3];
    #pragma unroll
    for (int a = 0; a < 3; a++) {
        int idx = tid + a * 256;
        int pl  = (idx >= 384);
        int rem = idx - (pl ? 384 : 0);      // idx mod 384 (384 != pow2!)
        int r   = rem >> 2, ch = rem & 3;
        int grow = (r >> 5) * 512 + cblk * 32 + (r & 31);
        wsrc[a]  = (const char*)(pl ? g_wl : g_wh) + (size_t)grow * 2048 + ch * 16;
        wdst0[a] = 4 * XB + (pl ? 2 * WB : 0) + r * 80 + ch * 16;
    }

    // ---- fragment base addresses ----
    int lane15 = lane & 15;
    u32 a_h = sb + (u32)((wm * (MT * 16) + lane15) * 80 + (lane >> 4) * 16);
    u32 a_l = a_h + 2 * XB;
    u32 b_h = sb + 4 * XB + (u32)((wn * 16 + (lane & 7)) * 80 + ((lane >> 3) & 1) * 16);
    u32 b_l = b_h + 2 * WB;

    float acc[MT][3][2][4];
    #pragma unroll
    for (int mt = 0; mt < MT; mt++)
        #pragma unroll
        for (int g = 0; g < 3; g++)
            #pragma unroll
            for (int hf = 0; hf < 2; hf++)
                #pragma unroll
                for (int q = 0; q < 4; q++) acc[mt][g][hf][q] = 0.0f;

    #pragma unroll
    for (int a = 0; a < XLD; a++) cpa16(sb + xdst0[a], xsrc[a]);
    #pragma unroll
    for (int a = 0; a < 3; a++) cpa16(sb + wdst0[a], wsrc[a]);
    cp_commit();

    for (int t = 0; t < NT; t++) {
        int buf = t & 1;
        if (t + 1 < NT) {
            int nb = (t + 1) & 1;
            size_t off = (size_t)(t + 1) * 64;
            #pragma unroll
            for (int a = 0; a < XLD; a++) cpa16(sb + xdst0[a] + nb * XB, xsrc[a] + off);
            #pragma unroll
            for (int a = 0; a < 3; a++) cpa16(sb + wdst0[a] + nb * WB, wsrc[a] + off);
            cp_commit();
            cp_wait<1>();
        } else {
            cp_wait<0>();
        }
        __syncthreads();

        u32 xoff = buf * XB, woff = buf * WB;
        #pragma unroll
        for (int j = 0; j < 2; j++) {
            u32 bh[3][2][2], bl[3][2][2];
            #pragma unroll
            for (int g = 0; g < 3; g++)
                #pragma unroll
                for (int hf = 0; hf < 2; hf++) {
                    u32 ba = (u32)(g * 2560 + hf * 640 + j * 32);
                    ldsm2(bh[g][hf][0], bh[g][hf][1], b_h + woff + ba);
                    ldsm2(bl[g][hf][0], bl[g][hf][1], b_l + woff + ba);
                }
            #pragma unroll
            for (int mt = 0; mt < MT; mt++) {
                u32 ah[4], al[4];
                u32 aa = (u32)(mt * 1280 + j * 32);
                ldsm4(ah[0], ah[1], ah[2], ah[3], a_h + xoff + aa);
                ldsm4(al[0], al[1], al[2], al[3], a_l + xoff + aa);
                // term-outer: same-accumulator MMAs spaced by 6 independents
                #pragma unroll
                for (int term = 0; term < 3; term++)
                    #pragma unroll
                    for (int g = 0; g < 3; g++)
                        #pragma unroll
                        for (int hf = 0; hf < 2; hf++) {
                            const u32* af = (term == 2) ? al : ah;
                            const u32* bf = (term == 1) ? bl[g][hf] : bh[g][hf];
                            mma16816(acc[mt][g][hf], af, bf);
                        }
            }
        }
        __syncthreads();
    }

    // ---- fused gate epilogue; write next level's bf16 hi/lo planes ----
    int gid = lane >> 2, tig = lane & 3;
    #pragma unroll
    for (int mt = 0; mt < MT; mt++) {
        #pragma unroll
        for (int hf = 0; hf < 2; hf++) {
            int ch = cblk * 32 + wn * 16 + hf * 8 + 2 * tig;
            float bl0 = bias[ch],        bl1 = bias[ch + 1];
            float br0 = bias[512 + ch],  br1 = bias[513 + ch];
            float bg0 = bias[1024 + ch], bg1 = bias[1025 + ch];
            #pragma unroll
            for (int rs = 0; rs < 2; rs++) {
                int pos = p0 + wm * (MT * 16) + mt * 16 + rs * 8 + gid;
                if (pos >= P) continue;
                float lv0 = acc[mt][0][hf][rs * 2 + 0] + bl0;
                float lv1 = acc[mt][0][hf][rs * 2 + 1] + bl1;
                float rv0 = tanhf(acc[mt][1][hf][rs * 2 + 0] + br0);
                float rv1 = tanhf(acc[mt][1][hf][rs * 2 + 1] + br1);
                float gv0 = 1.0f / (1.0f + expf(-(acc[mt][2][hf][rs * 2 + 0] + bg0)));
                float gv1 = 1.0f / (1.0f + expf(-(acc[mt][2][hf][rs * 2 + 1] + bg1)));
                float v0 = lv0 * gv0 + rv0 * (1.0f - gv0);
                float v1 = lv1 * gv1 + rv1 * (1.0f - gv1);
                __nv_bfloat162 ph, pl2;
                split_bf16(v0, ph.x, pl2.x);
                split_bf16(v1, ph.y, pl2.y);
                *reinterpret_cast<__nv_bfloat162*>(outh + (size_t)pos * CCH + ch) = ph;
                *reinterpret_cast<__nv_bfloat162*>(outl + (size_t)pos * CCH + ch) = pl2;
            }
        }
    }
}

// ---------------------------------------------------------------------------
__global__ void extract(float* __restrict__ out, const int* __restrict__ Np) {
    int b = blockIdx.x;
    int N = Np[b];
    int s = 31 - __clz(N);
    int off = SLAB - (SLAB >> s);
    int c = threadIdx.x;
    size_t idx = ((size_t)b * SLAB + off) * CCH + c;
    out[b * CCH + c] = __bfloat162float(g_xh[idx]) + __bfloat162float(g_xl[idx]);
}

// ---------------------------------------------------------------------------
static inline void launch_level(const int* N, const float* bias, int level,
                                int off_in, int off_out, int maxP) {
    if (maxP >= 128) {
        constexpr int SM = 4 * (128 * PITCH * 2) + 4 * WB;   // 71680
        dim3 g((maxP + 127) / 128, 16, BATCH);
        conv_mma<2><<<g, 256, SM>>>(N, bias, level, off_in, off_out, maxP);
    } else {
        constexpr int SM = 4 * (64 * PITCH * 2) + 4 * WB;    // 51200
        dim3 g((maxP + 63) / 64, 16, BATCH);
        conv_mma<1><<<g, 256, SM>>>(N, bias, level, off_in, off_out, maxP);
    }
}

extern "C" void kernel_launch(void* const* d_in, const int* in_sizes, int n_in,
                              void* d_out, int out_size) {
    const float* h    = (const float*)d_in[0];
    const float* W    = (const float*)d_in[1];
    const float* bias = (const float*)d_in[2];
    const int*   N    = (const int*)d_in[3];
    float* out = (float*)d_out;

    cudaFuncSetAttribute(conv_mma<2>, cudaFuncAttributeMaxDynamicSharedMemorySize,
                         4 * (128 * PITCH * 2) + 4 * WB);
    cudaFuncSetAttribute(conv_mma<1>, cudaFuncAttributeMaxDynamicSharedMemorySize,
                         4 * (64 * PITCH * 2) + 4 * WB);

    permute_w<<<(1536 * KDIM + 255) / 256, 256>>>(W);

    dim3 tg(LMAX / 32, CCH / 32, BATCH);
    transpose_init<<<tg, 256>>>(h, N);

    // level 0: partial fold (P_b = N - Nfp2 <= 2047), input = staging @ row 4096
    launch_level(N, bias, 0, 4096, 0, 2048);

    // tree levels
    int off_in = 0;
    for (int k = 1; k <= 12; k++) {
        int off_out = SLAB - (SLAB >> k);
        int maxP = LMAX >> k;
        launch_level(N, bias, k, off_in, off_out, maxP);
        off_in = off_out;
    }

    extract<<<BATCH, CCH>>>(out, N);
}

// round 9
// speedup vs baseline: 3.7218x; 1.0279x over previous
#include <cuda_runtime.h>
#include <cuda_bf16.h>
#include <math.h>

// ---------------------------------------------------------------------------
// Tree-reduce with fused conv gate — tensor cores (bf16x3 split), v3b.
//   xh*wh + xh*wl + xl*wh with fp32 accum (mma.sync.m16n8k16.bf16).
// v3 vs round-6 winner: 3-stage cp.async pipeline (prefetch distance 2),
// one __syncthreads per k-tile. 2 CTAs/SM (107.5 KB smem/CTA).
// v3b fix: final-iteration cp.async drain — at t = NT-1 the only pending
// group is group NT-1 itself, so wait_group<1> returned early and the last
// k-tile raced its own loads (rel_err 8e-3). Now wait<0> on the last tile.
// (tcgen05 unavailable: harness compiles .target sm_100, non-'a'.)
// ---------------------------------------------------------------------------

#define BATCH 16
#define CCH   512
#define LMAX  4096
#define KDIM  1024
#define SLAB  8192
#define BK    32
#define NT    (KDIM / BK)         // 32 k-tiles
#define WPL   (96 * 80)           // 7680 B per w plane per stage

__device__ __nv_bfloat16 g_xh[(size_t)BATCH * SLAB * CCH];
__device__ __nv_bfloat16 g_xl[(size_t)BATCH * SLAB * CCH];
__device__ __nv_bfloat16 g_wh[1536 * KDIM];
__device__ __nv_bfloat16 g_wl[1536 * KDIM];

typedef unsigned u32;

__device__ __forceinline__ void cpa16(u32 dst, const void* src) {
    asm volatile("cp.async.cg.shared.global [%0], [%1], 16;" :: "r"(dst), "l"(src));
}
__device__ __forceinline__ void cp_commit() {
    asm volatile("cp.async.commit_group;");
}
template<int NW> __device__ __forceinline__ void cp_wait() {
    asm volatile("cp.async.wait_group %0;" :: "n"(NW));
}
__device__ __forceinline__ void ldsm4(u32& r0, u32& r1, u32& r2, u32& r3, u32 a) {
    asm volatile("ldmatrix.sync.aligned.m8n8.x4.shared.b16 {%0,%1,%2,%3}, [%4];"
                 : "=r"(r0), "=r"(r1), "=r"(r2), "=r"(r3) : "r"(a));
}
__device__ __forceinline__ void ldsm2(u32& r0, u32& r1, u32 a) {
    asm volatile("ldmatrix.sync.aligned.m8n8.x2.shared.b16 {%0,%1}, [%2];"
                 : "=r"(r0), "=r"(r1) : "r"(a));
}
__device__ __forceinline__ void mma16816(float* d, const u32* a, const u32* b) {
    asm volatile("mma.sync.aligned.m16n8k16.row.col.f32.bf16.bf16.f32 "
                 "{%0,%1,%2,%3},{%4,%5,%6,%7},{%8,%9},{%0,%1,%2,%3};"
                 : "+f"(d[0]), "+f"(d[1]), "+f"(d[2]), "+f"(d[3])
                 : "r"(a[0]), "r"(a[1]), "r"(a[2]), "r"(a[3]),
                   "r"(b[0]), "r"(b[1]));
}
__device__ __forceinline__ void split_bf16(float v, __nv_bfloat16& h, __nv_bfloat16& l) {
    h = __float2bfloat16(v);
    l = __float2bfloat16(v - __bfloat162float(h));
}

// ---------------------------------------------------------------------------
__global__ void permute_w(const float* __restrict__ W) {
    int i = blockIdx.x * blockDim.x + threadIdx.x;
    if (i >= 1536 * KDIM) return;
    int o  = i >> 10;
    int kp = i & 1023;
    int kk = kp >> 9;
    int c  = kp & 511;
    float w = W[o * KDIM + c * 2 + kk];
    split_bf16(w, g_wh[i], g_wl[i]);
}

// ---------------------------------------------------------------------------
__global__ void transpose_init(const float* __restrict__ h,
                               const int* __restrict__ Np) {
    __shared__ float tile[32][33];
    int b = blockIdx.z;
    int N = Np[b];
    int s = 31 - __clz(N);
    int Nfp2 = 1 << s;
    int M2 = N - Nfp2;
    int M  = 2 * M2;
    int j0 = blockIdx.x * 32;
    int c0 = blockIdx.y * 32;
    if (j0 >= N) return;

    int tx = threadIdx.x & 31, ty = threadIdx.x >> 5;
    const float* hb = h + (size_t)b * CCH * LMAX;
    #pragma unroll
    for (int i = 0; i < 4; i++) {
        int c = c0 + ty + i * 8;
        tile[ty + i * 8][tx] = hb[(size_t)c * LMAX + j0 + tx];
    }
    __syncthreads();
    size_t slab = (size_t)b * SLAB;
    #pragma unroll
    for (int i = 0; i < 4; i++) {
        int j = j0 + ty + i * 8;
        float v = tile[tx][ty + i * 8];
        int c = c0 + tx;
        size_t idx;
        if (j < M)        idx = (slab + 4096 + j) * CCH + c;
        else if (j < N)   idx = (slab + (j - M2)) * CCH + c;
        else continue;
        __nv_bfloat16 hv, lv;
        split_bf16(v, hv, lv);
        g_xh[idx] = hv;
        g_xl[idx] = lv;
    }
}

// ---------------------------------------------------------------------------
// MT = m16-tiles per warp; block tile = MT*64 positions x 96 rows.
// Warp grid 4(M) x 2(N). 3-stage cp.async pipeline.
// ---------------------------------------------------------------------------
template<int MT>
__global__ __launch_bounds__(256, 2)
void conv_mma(const int* __restrict__ Np, const float* __restrict__ bias,
              int level, int off_in, int off_out, int maxP) {
    constexpr int BM   = MT * 64;
    constexpr int XPL  = BM * 80;                 // one x plane per stage
    constexpr int STG  = 2 * XPL + 2 * WPL;       // bytes per stage
    constexpr int XCH  = BM * 4;                  // chunks per x plane
    constexpr int XLD  = 2 * MT;                  // x cp.async per thread

    extern __shared__ char smem[];
    int b = blockIdx.z;
    int N = Np[b];
    int s = 31 - __clz(N);
    int Nfp2 = 1 << s;
    int P;
    if (level == 0) P = N - Nfp2;
    else { int li = Nfp2 >> (level - 1); P = (li >= 2) ? (li >> 1) : 0; }
    int p0 = blockIdx.x * BM;
    if (p0 >= P) return;

    const __nv_bfloat16* inh = g_xh + ((size_t)b * SLAB + off_in) * CCH;
    const __nv_bfloat16* inl = g_xl + ((size_t)b * SLAB + off_in) * CCH;
    __nv_bfloat16* outh = g_xh + ((size_t)b * SLAB + off_out) * CCH;
    __nv_bfloat16* outl = g_xl + ((size_t)b * SLAB + off_out) * CCH;
    int cblk = blockIdx.y;

    u32 sb = (u32)__cvta_generic_to_shared(smem);
    int tid = threadIdx.x, lane = tid & 31, wid = tid >> 5;
    int wm = wid >> 1, wn = wid & 1;

    // ---- load plans (offsets within a stage) ----
    const char* xsrc[XLD]; u32 xoff0[XLD];
    #pragma unroll
    for (int a = 0; a < XLD; a++) {
        int idx = tid + a * 256;
        int pl  = (idx >= XCH);
        int rem = idx - (pl ? XCH : 0);
        int pos = rem >> 2, ch = rem & 3;
        int lc = min(p0 + pos, maxP - 1);
        const __nv_bfloat16* base = pl ? inl : inh;
        xsrc[a]  = (const char*)base + (size_t)(2 * lc) * 1024 + ch * 16;
        xoff0[a] = (pl ? XPL : 0) + pos * 80 + ch * 16;
    }
    const char* wsrc[3]; u32 woff0[3];
    #pragma unroll
    for (int a = 0; a < 3; a++) {
        int idx = tid + a * 256;
        int pl  = (idx >= 384);
        int rem = idx - (pl ? 384 : 0);      // idx mod 384 (384 != pow2!)
        int r   = rem >> 2, ch = rem & 3;
        int grow = (r >> 5) * 512 + cblk * 32 + (r & 31);
        wsrc[a]  = (const char*)(pl ? g_wl : g_wh) + (size_t)grow * 2048 + ch * 16;
        woff0[a] = 2 * XPL + (pl ? WPL : 0) + r * 80 + ch * 16;
    }

    // stage fill: K-chunk t -> buffer sbase
    auto issue = [&](int t, u32 sbase) {
        size_t off = (size_t)t * 64;
        #pragma unroll
        for (int a = 0; a < XLD; a++) cpa16(sbase + xoff0[a], xsrc[a] + off);
        #pragma unroll
        for (int a = 0; a < 3; a++) cpa16(sbase + woff0[a], wsrc[a] + off);
        cp_commit();
    };

    // ---- fragment base offsets within a stage ----
    int lane15 = lane & 15;
    u32 a_h = (u32)((wm * (MT * 16) + lane15) * 80 + (lane >> 4) * 16);
    u32 a_l = a_h + XPL;
    u32 b_h = (u32)(2 * XPL + (wn * 16 + (lane & 7)) * 80 + ((lane >> 3) & 1) * 16);
    u32 b_l = b_h + WPL;

    float acc[MT][3][2][4];
    #pragma unroll
    for (int mt = 0; mt < MT; mt++)
        #pragma unroll
        for (int g = 0; g < 3; g++)
            #pragma unroll
            for (int hf = 0; hf < 2; hf++)
                #pragma unroll
                for (int q = 0; q < 4; q++) acc[mt][g][hf][q] = 0.0f;

    // prologue: stages 0 and 1
    issue(0, sb);
    issue(1, sb + STG);

    u32 bufc = 0, bufp = 2 * STG;      // compute buffer, prefetch buffer offsets
    for (int t = 0; t < NT; t++) {
        // drain so that group t is complete: for t < NT-1 exactly one younger
        // group is in flight (wait<1>); at t = NT-1 group t is the ONLY
        // pending group, so we must wait<0> (v3 raced here).
        if (t < NT - 1) cp_wait<1>(); else cp_wait<0>();
        __syncthreads();               // data visible; compute t-1 fully done
        if (t + 2 < NT) {
            issue(t + 2, sb + bufp);
            bufp = (bufp == 2 * STG) ? 0 : bufp + STG;
        }

        u32 cb = sb + bufc;
        bufc = (bufc == 2 * STG) ? 0 : bufc + STG;
        #pragma unroll
        for (int j = 0; j < 2; j++) {
            u32 bh[3][2][2], bl[3][2][2];
            #pragma unroll
            for (int g = 0; g < 3; g++)
                #pragma unroll
                for (int hf = 0; hf < 2; hf++) {
                    u32 ba = (u32)(g * 2560 + hf * 640 + j * 32);
                    ldsm2(bh[g][hf][0], bh[g][hf][1], cb + b_h + ba);
                    ldsm2(bl[g][hf][0], bl[g][hf][1], cb + b_l + ba);
                }
            #pragma unroll
            for (int mt = 0; mt < MT; mt++) {
                u32 ah[4], al[4];
                u32 aa = (u32)(mt * 1280 + j * 32);
                ldsm4(ah[0], ah[1], ah[2], ah[3], cb + a_h + aa);
                ldsm4(al[0], al[1], al[2], al[3], cb + a_l + aa);
                // term-outer: same-accumulator MMAs spaced by 6 independents
                #pragma unroll
                for (int term = 0; term < 3; term++)
                    #pragma unroll
                    for (int g = 0; g < 3; g++)
                        #pragma unroll
                        for (int hf = 0; hf < 2; hf++) {
                            const u32* af = (term == 2) ? al : ah;
                            const u32* bf = (term == 1) ? bl[g][hf] : bh[g][hf];
                            mma16816(acc[mt][g][hf], af, bf);
                        }
            }
        }
    }

    // ---- fused gate epilogue; write next level's bf16 hi/lo planes ----
    int gid = lane >> 2, tig = lane & 3;
    #pragma unroll
    for (int mt = 0; mt < MT; mt++) {
        #pragma unroll
        for (int hf = 0; hf < 2; hf++) {
            int ch = cblk * 32 + wn * 16 + hf * 8 + 2 * tig;
            float bl0 = bias[ch],        bl1 = bias[ch + 1];
            float br0 = bias[512 + ch],  br1 = bias[513 + ch];
            float bg0 = bias[1024 + ch], bg1 = bias[1025 + ch];
            #pragma unroll
            for (int rs = 0; rs < 2; rs++) {
                int pos = p0 + wm * (MT * 16) + mt * 16 + rs * 8 + gid;
                if (pos >= P) continue;
                float lv0 = acc[mt][0][hf][rs * 2 + 0] + bl0;
                float lv1 = acc[mt][0][hf][rs * 2 + 1] + bl1;
                float rv0 = tanhf(acc[mt][1][hf][rs * 2 + 0] + br0);
                float rv1 = tanhf(acc[mt][1][hf][rs * 2 + 1] + br1);
                float gv0 = 1.0f / (1.0f + expf(-(acc[mt][2][hf][rs * 2 + 0] + bg0)));
                float gv1 = 1.0f / (1.0f + expf(-(acc[mt][2][hf][rs * 2 + 1] + bg1)));
                float v0 = lv0 * gv0 + rv0 * (1.0f - gv0);
                float v1 = lv1 * gv1 + rv1 * (1.0f - gv1);
                __nv_bfloat162 ph, pl2;
                split_bf16(v0, ph.x, pl2.x);
                split_bf16(v1, ph.y, pl2.y);
                *reinterpret_cast<__nv_bfloat162*>(outh + (size_t)pos * CCH + ch) = ph;
                *reinterpret_cast<__nv_bfloat162*>(outl + (size_t)pos * CCH + ch) = pl2;
            }
        }
    }
}

// ---------------------------------------------------------------------------
__global__ void extract(float* __restrict__ out, const int* __restrict__ Np) {
    int b = blockIdx.x;
    int N = Np[b];
    int s = 31 - __clz(N);
    int off = SLAB - (SLAB >> s);
    int c = threadIdx.x;
    size_t idx = ((size_t)b * SLAB + off) * CCH + c;
    out[b * CCH + c] = __bfloat162float(g_xh[idx]) + __bfloat162float(g_xl[idx]);
}

// ---------------------------------------------------------------------------
#define SMEM_MT2 (3 * (2 * (128 * 80) + 2 * WPL))   // 107520
#define SMEM_MT1 (3 * (2 * (64 * 80) + 2 * WPL))    // 76800

static inline void launch_level(const int* N, const float* bias, int level,
                                int off_in, int off_out, int maxP) {
    if (maxP >= 128) {
        dim3 g((maxP + 127) / 128, 16, BATCH);
        conv_mma<2><<<g, 256, SMEM_MT2>>>(N, bias, level, off_in, off_out, maxP);
    } else {
        dim3 g((maxP + 63) / 64, 16, BATCH);
        conv_mma<1><<<g, 256, SMEM_MT1>>>(N, bias, level, off_in, off_out, maxP);
    }
}

extern "C" void kernel_launch(void* const* d_in, const int* in_sizes, int n_in,
                              void* d_out, int out_size) {
    const float* h    = (const float*)d_in[0];
    const float* W    = (const float*)d_in[1];
    const float* bias = (const float*)d_in[2];
    const int*   N    = (const int*)d_in[3];
    float* out = (float*)d_out;

    cudaFuncSetAttribute(conv_mma<2>, cudaFuncAttributeMaxDynamicSharedMemorySize,
                         SMEM_MT2);
    cudaFuncSetAttribute(conv_mma<1>, cudaFuncAttributeMaxDynamicSharedMemorySize,
                         SMEM_MT1);

    permute_w<<<(1536 * KDIM + 255) / 256, 256>>>(W);

    dim3 tg(LMAX / 32, CCH / 32, BATCH);
    transpose_init<<<tg, 256>>>(h, N);

    // level 0: partial fold (P_b = N - Nfp2 <= 2047), input = staging @ row 4096
    launch_level(N, bias, 0, 4096, 0, 2048);

    // tree levels
    int off_in = 0;
    for (int k = 1; k <= 12; k++) {
        int off_out = SLAB - (SLAB >> k);
        int maxP = LMAX >> k;
        launch_level(N, bias, k, off_in, off_out, maxP);
        off_in = off_out;
    }

    extract<<<BATCH, CCH>>>(out, N);
}